// round 16
// baseline (speedup 1.0000x reference)
#include <cuda_runtime.h>
#include <cuda_fp16.h>
#include <math.h>
#include <stdint.h>

// Problem constants (fixed for this dataset)
#define MAXN 30000
#define MAXE 480000
#define MAXNE (MAXE + MAXN)
#define HID 128
#define EPSV 1e-5f
#define DTV 0.1f
#define NSLOT 19
#define SLOT_ELEMS (128 * 128)

// ---------------- scratch (static device memory; no runtime allocs) ----------
__device__ int   g_deg[MAXN];
__device__ float g_dinv[MAXN];
__device__ int   g_rp[MAXN + 1];
__device__ int   g_cur[MAXN];
__device__ int   g_csrc[MAXNE];
__device__ float g_cw[MAXNE];
__device__ float g_stats[2 * HID];
__device__ int   g_lex[MAXN];
__device__ int   g_bsum[256];

__device__ __align__(16) __half g_h[(size_t)MAXN * HID];    // GEMM output (pre-aggregation), fp16
__device__ __align__(16) __half g_bufA[(size_t)MAXN * HID]; // pre-IN activations, fp16
__device__ __align__(16) float g_M0[(size_t)MAXN * HID];    // precomputed mesh @ W0[4:132]
__device__ __align__(16) float g_F[MAXN * 4];
__device__ __align__(16) float g_h4[MAXN * 4];

// fp16 GEMM operand buffers
__device__ __align__(16) __half g_A[(size_t)MAXN * HID];
__device__ __align__(16) __half g_B[NSLOT * SLOT_ELEMS];

// ---------------- helpers -----------------------------------------------------
__device__ __forceinline__ uint32_t smem_u32(const void* p) {
    uint32_t a;
    asm("{ .reg .u64 t; cvta.to.shared.u64 t, %1; cvt.u32.u64 %0, t; }" : "=r"(a) : "l"(p));
    return a;
}

__device__ __forceinline__ void ldmx4(uint32_t* r, uint32_t addr) {
    asm volatile("ldmatrix.sync.aligned.m8n8.x4.shared.b16 {%0,%1,%2,%3}, [%4];"
                 : "=r"(r[0]), "=r"(r[1]), "=r"(r[2]), "=r"(r[3]) : "r"(addr));
}

__device__ __forceinline__ void mma16816(float* c, const uint32_t* a, uint32_t b0, uint32_t b1) {
    asm volatile("mma.sync.aligned.m16n8k16.row.col.f32.f16.f16.f32 "
                 "{%0,%1,%2,%3}, {%4,%5,%6,%7}, {%8,%9}, {%0,%1,%2,%3};"
                 : "+f"(c[0]), "+f"(c[1]), "+f"(c[2]), "+f"(c[3])
                 : "r"(a[0]), "r"(a[1]), "r"(a[2]), "r"(a[3]), "r"(b0), "r"(b1));
}

__device__ __forceinline__ void half_store4(float4 v, __half* p) {
    __half2 h01 = __floats2half2_rn(v.x, v.y);
    __half2 h23 = __floats2half2_rn(v.z, v.w);
    uint2 pk;
    pk.x = *(uint32_t*)&h01; pk.y = *(uint32_t*)&h23;
    *(uint2*)p = pk;
}

__device__ __forceinline__ void acc_row(float4& acc, uint2 raw, float w) {
    float2 f01 = __half22float2(*(__half2*)&raw.x);
    float2 f23 = __half22float2(*(__half2*)&raw.y);
    acc.x += w * f01.x; acc.y += w * f01.y;
    acc.z += w * f23.x; acc.w += w * f23.y;
}

// ---------------- graph preprocessing ----------------------------------------
__global__ void k_init_deg(int n) {
    int i = blockIdx.x * blockDim.x + threadIdx.x;
    if (i < n) g_deg[i] = 1;  // self-loop
}

__global__ void k_count(const int* __restrict__ ei, int E) {
    int e = blockIdx.x * blockDim.x + threadIdx.x;
    if (e < E) atomicAdd(&g_deg[ei[E + e]], 1);
}

__global__ void k_dinv(int n) {
    int i = blockIdx.x * blockDim.x + threadIdx.x;
    if (i < n) g_dinv[i] = rsqrtf((float)g_deg[i]);
}

// multi-block exclusive scan: scan1 (local) -> scan2 (block sums) -> scan3 (add)
__global__ void k_scan1(int n) {
    __shared__ int ws[8];
    int b = blockIdx.x, t = threadIdx.x;
    int i = b * 256 + t;
    int lane = t & 31, w = t >> 5;
    int v = (i < n) ? g_deg[i] : 0;
    int x = v;
    #pragma unroll
    for (int o = 1; o < 32; o <<= 1) {
        int t2 = __shfl_up_sync(0xFFFFFFFFu, x, o);
        if (lane >= o) x += t2;
    }
    if (lane == 31) ws[w] = x;
    __syncthreads();
    if (w == 0) {
        int s = (lane < 8) ? ws[lane] : 0;
        #pragma unroll
        for (int o = 1; o < 8; o <<= 1) {
            int t2 = __shfl_up_sync(0xFFFFFFFFu, s, o);
            if (lane >= o) s += t2;
        }
        if (lane < 8) ws[lane] = s;
    }
    __syncthreads();
    int woff = (w > 0) ? ws[w - 1] : 0;
    if (i < n) g_lex[i] = woff + x - v;
    if (t == 255) g_bsum[b] = woff + x;
}

__global__ void k_scan2(int nb, int n) {
    __shared__ int ws[8];
    int t = threadIdx.x;
    int lane = t & 31, w = t >> 5;
    int v = (t < nb) ? g_bsum[t] : 0;
    int x = v;
    #pragma unroll
    for (int o = 1; o < 32; o <<= 1) {
        int t2 = __shfl_up_sync(0xFFFFFFFFu, x, o);
        if (lane >= o) x += t2;
    }
    if (lane == 31) ws[w] = x;
    __syncthreads();
    if (w == 0) {
        int s = (lane < 8) ? ws[lane] : 0;
        #pragma unroll
        for (int o = 1; o < 8; o <<= 1) {
            int t2 = __shfl_up_sync(0xFFFFFFFFu, s, o);
            if (lane >= o) s += t2;
        }
        if (lane < 8) ws[lane] = s;
    }
    __syncthreads();
    int woff = (w > 0) ? ws[w - 1] : 0;
    int excl = woff + x - v;
    __syncthreads();
    if (t < nb) g_bsum[t] = excl;
    if (t == nb - 1) g_rp[n] = woff + x;
}

__global__ void k_scan3(int n) {
    int i = blockIdx.x * blockDim.x + threadIdx.x;
    if (i < n) {
        int v = g_lex[i] + g_bsum[i >> 8];
        g_rp[i] = v;
        g_cur[i] = v;
    }
}

__global__ void k_fill(const int* __restrict__ ei, int E, int n) {
    int idx = blockIdx.x * blockDim.x + threadIdx.x;
    if (idx < E) {
        int s = ei[idx], d = ei[E + idx];
        int pos = atomicAdd(&g_cur[d], 1);
        g_csrc[pos] = s;
        g_cw[pos] = g_dinv[s] * g_dinv[d];
    } else if (idx < E + n) {
        int i = idx - E;
        int pos = atomicAdd(&g_cur[i], 1);
        g_csrc[pos] = i;
        g_cw[pos] = g_dinv[i] * g_dinv[i];
    }
}

// ---------------- weight conversion: W[KxN] fp32 -> B[NxKpad] fp16 -----------
struct WTab {
    const float* src[NSLOT];
    int K[NSLOT];
    int Kp[NSLOT];
};

__global__ void k_wconv(WTab t) {
    int slot = blockIdx.y;
    int Kp = t.Kp[slot];
    int idx = blockIdx.x * 256 + threadIdx.x;
    if (idx >= 128 * Kp) return;
    int nrow = idx / Kp, k = idx % Kp;
    float v = (k < t.K[slot]) ? t.src[slot][(size_t)k * 128 + nrow] : 0.0f;
    g_B[slot * SLOT_ELEMS + idx] = __float2half(v);
}

// meshfield [Nx8] fp32 -> fp16 [Nx16] (cols 8..15 zero)
__global__ void k_meshin(const float* __restrict__ mf, int n) {
    int idx = blockIdx.x * blockDim.x + threadIdx.x;
    if (idx >= n * 16) return;
    int node = idx >> 4, c = idx & 15;
    float v = (c < 8) ? mf[node * 8 + c] : 0.0f;
    g_A[idx] = __float2half(v);
}

// ---------------- mma.sync fp16 GEMM, M-tile 128 ------------------------------
#define SMS 136                         // smem row stride in halves (128 + 8 pad)
#define SM_A 0
#define SM_B (128 * SMS * 2)            // 34816
#define GEMM_SMEM (SM_B + 128 * SMS * 2)  // 69632 bytes

__global__ __launch_bounds__(256) void k_mmagemm(
    const __half* __restrict__ A, const __half* __restrict__ B,
    void* __restrict__ outp, int n, int K, int out_half)
{
    extern __shared__ __align__(16) char smem[];
    int tid = threadIdx.x;
    int m0 = blockIdx.x * 128;
    int nb8 = K >> 3;

    for (int idx = tid; idx < 128 * nb8; idx += 256) {
        int r = idx / nb8, c = idx - r * nb8;
        uint4 v = *(const uint4*)(B + (size_t)r * K + c * 8);
        *(uint4*)(smem + SM_B + (r * SMS + c * 8) * 2) = v;
    }
    for (int idx = tid; idx < 128 * nb8; idx += 256) {
        int r = idx / nb8, c = idx - r * nb8;
        int gr = m0 + r;
        uint4 v = make_uint4(0, 0, 0, 0);
        if (gr < n) v = *(const uint4*)(A + (size_t)gr * K + c * 8);
        *(uint4*)(smem + SM_A + (r * SMS + c * 8) * 2) = v;
    }
    __syncthreads();

    uint32_t sb = smem_u32(smem);
    int wid = tid >> 5, lane = tid & 31;
    int rowbase = wid * 16;

    int a_row  = (lane & 7) + ((lane >> 3) & 1) * 8;
    int a_koff = (lane >> 4) * 8;
    int b_nrow = ((lane >> 4) * 8) + (lane & 7);
    int b_koff = ((lane >> 3) & 1) * 8;

    float acc[16][4];
    #pragma unroll
    for (int j = 0; j < 16; j++)
        #pragma unroll
        for (int q = 0; q < 4; q++) acc[j][q] = 0.f;

    int ksteps = K >> 4;
    for (int ks = 0; ks < ksteps; ks++) {
        uint32_t a0[4];
        uint32_t aaddr = sb + SM_A + (uint32_t)(((rowbase + a_row) * SMS + a_koff + ks * 16) * 2);
        ldmx4(a0, aaddr);
        #pragma unroll
        for (int p = 0; p < 8; p++) {
            uint32_t b[4];
            uint32_t baddr = sb + SM_B + (uint32_t)(((p * 16 + b_nrow) * SMS + b_koff + ks * 16) * 2);
            ldmx4(b, baddr);
            mma16816(acc[2 * p + 0], a0, b[0], b[1]);
            mma16816(acc[2 * p + 1], a0, b[2], b[3]);
        }
    }

    int g = lane >> 2, i4 = lane & 3;
    int r0 = m0 + rowbase + g;
    if (out_half) {
        __half* out = (__half*)outp;
        #pragma unroll
        for (int nt = 0; nt < 16; nt++) {
            int col = nt * 8 + i4 * 2;
            if (r0 < n)
                *(__half2*)(out + (size_t)r0 * 128 + col) =
                    __floats2half2_rn(acc[nt][0], acc[nt][1]);
            if (r0 + 8 < n)
                *(__half2*)(out + (size_t)(r0 + 8) * 128 + col) =
                    __floats2half2_rn(acc[nt][2], acc[nt][3]);
        }
    } else {
        float* out = (float*)outp;
        #pragma unroll
        for (int nt = 0; nt < 16; nt++) {
            int col = nt * 8 + i4 * 2;
            if (r0 < n)
                *(float2*)(out + (size_t)r0 * 128 + col) = make_float2(acc[nt][0], acc[nt][1]);
            if (r0 + 8 < n)
                *(float2*)(out + (size_t)(r0 + 8) * 128 + col) = make_float2(acc[nt][2], acc[nt][3]);
        }
    }
}

// ---------------- aggregation: out[d] = b + sum_e w_e * h[src_e] (128 ch) ----
// h is fp16 (256B rows). mode 0: fp16 -> outPre (pre-IN) + zero stats (blk 0);
// mode 1: relu->fp16 outHalf; mode 3: tanh->fp16 outHalf
__global__ __launch_bounds__(256) void k_agg128(
    const __half* __restrict__ h, const float* __restrict__ bias,
    __half* __restrict__ outPre, __half* __restrict__ outHalf,
    int n, int mode)
{
    if (mode == 0 && blockIdx.x == 0) g_stats[threadIdx.x] = 0.f;  // fold zero_stats
    int node = blockIdx.x * 8 + (threadIdx.x >> 5);
    if (node >= n) return;
    int lane = threadIdx.x & 31;
    float4 acc = ((const float4*)bias)[lane];
    int e = g_rp[node], e1 = g_rp[node + 1];
    for (; e + 8 <= e1; e += 8) {
        int s[8]; float w[8]; uint2 r[8];
        #pragma unroll
        for (int q = 0; q < 8; q++) { s[q] = g_csrc[e + q]; w[q] = g_cw[e + q]; }
        #pragma unroll
        for (int q = 0; q < 8; q++) r[q] = ((const uint2*)(h + (size_t)s[q] * 128))[lane];
        #pragma unroll
        for (int q = 0; q < 8; q++) acc_row(acc, r[q], w[q]);
    }
    for (; e + 4 <= e1; e += 4) {
        int s[4]; float w[4]; uint2 r[4];
        #pragma unroll
        for (int q = 0; q < 4; q++) { s[q] = g_csrc[e + q]; w[q] = g_cw[e + q]; }
        #pragma unroll
        for (int q = 0; q < 4; q++) r[q] = ((const uint2*)(h + (size_t)s[q] * 128))[lane];
        #pragma unroll
        for (int q = 0; q < 4; q++) acc_row(acc, r[q], w[q]);
    }
    for (; e < e1; ++e) {
        int s = g_csrc[e]; float w = g_cw[e];
        uint2 rv = ((const uint2*)(h + (size_t)s * 128))[lane];
        acc_row(acc, rv, w);
    }
    if (mode == 0) {
        half_store4(acc, outPre + (size_t)node * 128 + lane * 4);
    } else {
        if (mode == 1) {
            acc.x = fmaxf(acc.x, 0.f); acc.y = fmaxf(acc.y, 0.f);
            acc.z = fmaxf(acc.z, 0.f); acc.w = fmaxf(acc.w, 0.f);
        } else if (mode == 3) {
            acc.x = tanhf(acc.x); acc.y = tanhf(acc.y);
            acc.z = tanhf(acc.z); acc.w = tanhf(acc.w);
        }
        half_store4(acc, outHalf + (size_t)node * 128 + lane * 4);
    }
}

// ---------------- FUSED final conv9 front-half: h4 = (agg(h)+b) @ W9 ----------
__global__ __launch_bounds__(256) void k_agg_h4(
    const __half* __restrict__ h, const float* __restrict__ bias,
    const float* __restrict__ W9, float* __restrict__ h4, int n)
{
    int node = blockIdx.x * 8 + (threadIdx.x >> 5);
    if (node >= n) return;
    int lane = threadIdx.x & 31;
    float4 acc = ((const float4*)bias)[lane];
    int e = g_rp[node], e1 = g_rp[node + 1];
    for (; e + 8 <= e1; e += 8) {
        int s[8]; float w[8]; uint2 r[8];
        #pragma unroll
        for (int q = 0; q < 8; q++) { s[q] = g_csrc[e + q]; w[q] = g_cw[e + q]; }
        #pragma unroll
        for (int q = 0; q < 8; q++) r[q] = ((const uint2*)(h + (size_t)s[q] * 128))[lane];
        #pragma unroll
        for (int q = 0; q < 8; q++) acc_row(acc, r[q], w[q]);
    }
    for (; e + 4 <= e1; e += 4) {
        int s[4]; float w[4]; uint2 r[4];
        #pragma unroll
        for (int q = 0; q < 4; q++) { s[q] = g_csrc[e + q]; w[q] = g_cw[e + q]; }
        #pragma unroll
        for (int q = 0; q < 4; q++) r[q] = ((const uint2*)(h + (size_t)s[q] * 128))[lane];
        #pragma unroll
        for (int q = 0; q < 4; q++) acc_row(acc, r[q], w[q]);
    }
    for (; e < e1; ++e) {
        int s = g_csrc[e]; float w = g_cw[e];
        uint2 rv = ((const uint2*)(h + (size_t)s * 128))[lane];
        acc_row(acc, rv, w);
    }
    const float4* Wv = (const float4*)W9;
    float4 w0 = Wv[lane * 4 + 0], w1 = Wv[lane * 4 + 1];
    float4 w2 = Wv[lane * 4 + 2], w3 = Wv[lane * 4 + 3];
    float4 p;
    p.x = acc.x * w0.x + acc.y * w1.x + acc.z * w2.x + acc.w * w3.x;
    p.y = acc.x * w0.y + acc.y * w1.y + acc.z * w2.y + acc.w * w3.y;
    p.z = acc.x * w0.z + acc.y * w1.z + acc.z * w2.z + acc.w * w3.z;
    p.w = acc.x * w0.w + acc.y * w1.w + acc.z * w2.w + acc.w * w3.w;
    #pragma unroll
    for (int o = 16; o > 0; o >>= 1) {
        p.x += __shfl_xor_sync(0xFFFFFFFFu, p.x, o);
        p.y += __shfl_xor_sync(0xFFFFFFFFu, p.y, o);
        p.z += __shfl_xor_sync(0xFFFFFFFFu, p.z, o);
        p.w += __shfl_xor_sync(0xFFFFFFFFu, p.w, o);
    }
    if (lane == 0) ((float4*)h4)[node] = p;
}

// ---------------- instance norm (fp16 input) ----------------------------------
__global__ __launch_bounds__(128) void k_in_stats(const __half* __restrict__ x, int n) {
    int c = threadIdx.x;
    int chunk = (n + gridDim.x - 1) / gridDim.x;
    int r0 = blockIdx.x * chunk;
    int r1 = min(n, r0 + chunk);
    float s = 0.f, q = 0.f;
    for (int r = r0; r < r1; ++r) {
        float v = __half2float(x[(size_t)r * HID + c]);
        s += v; q += v * v;
    }
    atomicAdd(&g_stats[c], s);
    atomicAdd(&g_stats[HID + c], q);
}

// apply IN, then ReLU, write fp16 (feeds first middle conv)
__global__ void k_in_apply_half(const __half* __restrict__ x, int n) {
    int idx = blockIdx.x * blockDim.x + threadIdx.x;
    if (idx >= n * HID) return;
    int c = idx & (HID - 1);
    float inv_n = 1.f / (float)n;
    float m = g_stats[c] * inv_n;
    float v = g_stats[HID + c] * inv_n - m * m;
    float y = (__half2float(x[idx]) - m) * rsqrtf(v + EPSV);
    y = fmaxf(y, 0.f);
    g_A[idx] = __float2half(y);
}

// ---------------- misc small kernels ------------------------------------------
__global__ void k_copyF0(const float* __restrict__ F0, int n) {
    int i = blockIdx.x * blockDim.x + threadIdx.x;
    if (i < n) ((float4*)g_F)[i] = ((const float4*)F0)[i];
}

// h = F @ W0[0:4] + M0   (diff conv0, mesh part precomputed), fp16 out
__global__ __launch_bounds__(256) void k_conv0_diff(const float* __restrict__ W0, int n) {
    int node = blockIdx.x * 8 + (threadIdx.x >> 5);
    if (node >= n) return;
    int lane = threadIdx.x & 31;
    float4 Fv = ((const float4*)g_F)[node];
    float4 m = ((const float4*)(g_M0 + (size_t)node * 128))[lane];
    const float4* w = (const float4*)W0;
    float4 w0 = w[0 * 32 + lane], w1 = w[1 * 32 + lane];
    float4 w2 = w[2 * 32 + lane], w3 = w[3 * 32 + lane];
    m.x += Fv.x * w0.x + Fv.y * w1.x + Fv.z * w2.x + Fv.w * w3.x;
    m.y += Fv.x * w0.y + Fv.y * w1.y + Fv.z * w2.y + Fv.w * w3.y;
    m.z += Fv.x * w0.z + Fv.y * w1.z + Fv.z * w2.z + Fv.w * w3.z;
    m.w += Fv.x * w0.w + Fv.y * w1.w + Fv.z * w2.w + Fv.w * w3.w;
    half_store4(m, g_h + (size_t)node * 128 + lane * 4);
}

// fused: 4-channel aggregation + bias + tanh -> F_dot; F update; write outputs
__global__ void k_agg4_step(const float* __restrict__ h4, const float* __restrict__ b,
                            float* __restrict__ out, int n, int T, int t)
{
    int i = blockIdx.x * blockDim.x + threadIdx.x;
    if (i >= n) return;
    float4 acc = *(const float4*)b;
    int e0 = g_rp[i], e1 = g_rp[i + 1];
    for (int e = e0; e < e1; ++e) {
        int s = g_csrc[e]; float w = g_cw[e];
        float4 hv = ((const float4*)h4)[s];
        acc.x += w * hv.x; acc.y += w * hv.y; acc.z += w * hv.z; acc.w += w * hv.w;
    }
    float4 fd;
    fd.x = tanhf(acc.x); fd.y = tanhf(acc.y);
    fd.z = tanhf(acc.z); fd.w = tanhf(acc.w);
    float4 fc = ((const float4*)g_F)[i];
    float4 fn;
    fn.x = tanhf(fc.x + fd.x * DTV);
    fn.y = tanhf(fc.y + fd.y * DTV);
    fn.z = tanhf(fc.z + fd.z * DTV);
    fn.w = tanhf(fc.w + fd.w * DTV);
    ((float4*)g_F)[i] = fn;
    float4* ob = (float4*)out;
    ob[(size_t)i * T + t] = fn;                     // Fs     [N][T][4]
    ob[(size_t)n * T + (size_t)i * T + t] = fd;     // F_dots [N][T][4]
}

// ---------------- host orchestration ------------------------------------------
extern "C" void kernel_launch(void* const* d_in, const int* in_sizes, int n_in,
                              void* d_out, int out_size)
{
    const float* F0    = (const float*)d_in[0];
    const int*   ei    = (const int*)d_in[1];
    const float* meshf = (const float*)d_in[2];
    const float* mW0   = (const float*)d_in[4];
    const float* mb0   = (const float*)d_in[5];
    const float* mWh   = (const float*)d_in[6];
    const float* mbh   = (const float*)d_in[7];
    const float* mW9   = (const float*)d_in[8];
    const float* mb9   = (const float*)d_in[9];
    const float* dW0   = (const float*)d_in[10];
    const float* db0   = (const float*)d_in[11];
    const float* dWh   = (const float*)d_in[12];
    const float* dbh   = (const float*)d_in[13];
    const float* dW9   = (const float*)d_in[14];
    const float* db9   = (const float*)d_in[15];
    float* out = (float*)d_out;

    int N = in_sizes[0] / 4;
    int E = in_sizes[1] / 2;
    int T = out_size / (2 * N * 4);
    if (N > MAXN || E > MAXE || T <= 0) return;

    float *M0buf, *h4;
    __half *hbuf, *bufA, *Abuf, *Bbuf;
    cudaGetSymbolAddress((void**)&hbuf,  g_h);
    cudaGetSymbolAddress((void**)&bufA,  g_bufA);
    cudaGetSymbolAddress((void**)&M0buf, g_M0);
    cudaGetSymbolAddress((void**)&h4,    g_h4);
    cudaGetSymbolAddress((void**)&Abuf,  g_A);
    cudaGetSymbolAddress((void**)&Bbuf,  g_B);

    cudaFuncSetAttribute(k_mmagemm, cudaFuncAttributeMaxDynamicSharedMemorySize, GEMM_SMEM);

    int gN = (N + 255) / 256;
    int gE = (E + 255) / 256;
    int gMM = (N + 127) / 128;   // GEMM M-tiles of 128
    int gA = (N + 7) / 8;
    int nb = (N + 255) / 256;

    // ---- graph preprocessing ----
    k_init_deg<<<gN, 256>>>(N);
    k_count<<<gE, 256>>>(ei, E);
    k_dinv<<<gN, 256>>>(N);
    k_scan1<<<nb, 256>>>(N);
    k_scan2<<<1, 256>>>(nb, N);
    k_scan3<<<gN, 256>>>(N);
    k_fill<<<(E + N + 255) / 256, 256>>>(ei, E, N);

    // ---- weight conversion (all 19 slots in one launch) ----
    WTab wt;
    wt.src[0] = mW0;  wt.K[0] = 8;   wt.Kp[0] = 16;            // mesh conv0
    for (int l = 0; l < 8; ++l) { wt.src[1 + l] = mWh + (size_t)l * HID * HID; wt.K[1 + l] = 128; wt.Kp[1 + l] = 128; }
    wt.src[9] = mW9;  wt.K[9] = 128; wt.Kp[9] = 128;           // mesh conv9
    for (int l = 0; l < 8; ++l) { wt.src[10 + l] = dWh + (size_t)l * HID * HID; wt.K[10 + l] = 128; wt.Kp[10 + l] = 128; }
    wt.src[18] = dW0 + 4 * HID; wt.K[18] = 128; wt.Kp[18] = 128;  // diff W0 mesh rows 4..131
    k_wconv<<<dim3(64, NSLOT), 256>>>(wt);

    // ---- mesh descriptor block ----
    k_meshin<<<(N * 16 + 255) / 256, 256>>>(meshf, N);
    k_mmagemm<<<gMM, 256, GEMM_SMEM>>>(Abuf, Bbuf, hbuf, N, 16, 1);
    k_agg128<<<gA, 256>>>(hbuf, mb0, bufA, Abuf, N, 0);
    k_in_stats<<<512, 128>>>(bufA, N);
    k_in_apply_half<<<(N * HID + 255) / 256, 256>>>(bufA, N);
    for (int l = 0; l < 8; ++l) {
        k_mmagemm<<<gMM, 256, GEMM_SMEM>>>(Abuf,
            Bbuf + (size_t)(1 + l) * SLOT_ELEMS, hbuf, N, 128, 1);
        k_agg128<<<gA, 256>>>(hbuf, mbh + (size_t)l * HID, bufA, Abuf, N, 1);
    }
    k_mmagemm<<<gMM, 256, GEMM_SMEM>>>(Abuf,
        Bbuf + (size_t)9 * SLOT_ELEMS, hbuf, N, 128, 1);
    k_agg128<<<gA, 256>>>(hbuf, mb9, bufA, Abuf, N, 3);   // tanh -> mesh fp16

    // ---- precompute M0 = mesh @ dW0[4:132]  (time-invariant, fp32) ----
    k_mmagemm<<<gMM, 256, GEMM_SMEM>>>(Abuf,
        Bbuf + (size_t)18 * SLOT_ELEMS, M0buf, N, 128, 0);

    // ---- time stepping ----
    k_copyF0<<<gN, 256>>>(F0, N);
    for (int t = 0; t < T; ++t) {
        k_conv0_diff<<<gA, 256>>>(dW0, N);
        k_agg128<<<gA, 256>>>(hbuf, db0, bufA, Abuf, N, 0);   // fp16 pre-IN + zero stats
        k_in_stats<<<512, 128>>>(bufA, N);
        k_in_apply_half<<<(N * HID + 255) / 256, 256>>>(bufA, N);
        for (int l = 0; l < 8; ++l) {
            k_mmagemm<<<gMM, 256, GEMM_SMEM>>>(Abuf,
                Bbuf + (size_t)(10 + l) * SLOT_ELEMS, hbuf, N, 128, 1);
            if (l < 7)
                k_agg128<<<gA, 256>>>(hbuf, dbh + (size_t)l * HID, bufA, Abuf, N, 1);
        }
        k_agg_h4<<<gA, 256>>>(hbuf, dbh + (size_t)7 * HID, dW9, h4, N);
        k_agg4_step<<<gN, 256>>>(h4, db9, out, N, T, t);
    }
}